// round 7
// baseline (speedup 1.0000x reference)
#include <cuda_runtime.h>
#include <cuda_bf16.h>

#define HGT 512
#define WID 512
#define BX  32
#define BY  4
#define RPT 8                    // rows (pixels) per thread (even)
#define NT  (BX*BY)              // 128 threads
#define TILE_W (BX + 2)          // 34
#define TILE_H (BY*RPT + 2)      // 34

// compare-exchange: a<-min, b<-max  (2x FMNMX, alu pipe)
#define CE(a,b) { float lo_ = fminf(a,b); float hi_ = fmaxf(a,b); a = lo_; b = hi_; }

// sort 3 in place (ascending)
#define SORT3(a,b,c) { CE(a,b) CE(a,c) CE(b,c) }

// Batcher merge of two sorted triples (a0<=a1<=a2, b0<=b1<=b2).
// After: ascending order is (a0, a2, a1, b0, b1, b2).   6 CE
#define MERGE33(a0,a1,a2,b0,b1,b2) \
    { CE(a0,b0) CE(a2,b2) CE(a2,b0) CE(a1,b1) CE(a2,a1) CE(b0,b1) }

// Batcher merge of sorted-6 (f0..f5 ascending) with sorted-3 (t0<=t1<=t2).
// After: ascending order is (f0, t0, f1, f2, t1, f4, f3, t2, f5).   12 CE
#define MERGE63(f0,f1,f2,f3,f4,f5,t0,t1,t2) { \
    CE(f0,t0) CE(t0,f4) CE(f2,t2) CE(t0,f2) CE(f4,t2) \
    CE(f1,t1) CE(t1,f5) CE(t1,f3) \
    CE(t0,f1) CE(f2,t1) CE(f4,f3) CE(t2,f5) }

// dot of the MERGE63 result (in its ascending register order) with weights
#define DOT63(f0,f1,f2,f3,f4,f5,t0,t1,t2) \
    ( fmaf(f0,W0, fmaf(t0,W1, f1*W2)) \
    + fmaf(f2,W3, fmaf(t1,W4, f4*W5)) \
    + fmaf(f3,W6, fmaf(t2,W7, f5*W8)) )

__global__ __launch_bounds__(NT, 10) void morph2d_kernel(
    const float* __restrict__ x,
    const float* __restrict__ se,
    const float* __restrict__ rnk,
    float* __restrict__ out)
{
    __shared__ float tile[TILE_H][TILE_W];
    __shared__ float s_w[9];     // exp(rank) numerators
    __shared__ float s_se[9];

    const int tx  = threadIdx.x;
    const int ty  = threadIdx.y;
    const int tid = ty * BX + tx;
    const int bb  = blockIdx.z;
    const int x0  = blockIdx.x * BX;
    const int y0  = blockIdx.y * (BY * RPT);

    const float* img = x + (size_t)bb * (HGT * WID);

    if (tid < 9) {
        s_w[tid]  = __expf(rnk[tid]);
        s_se[tid] = se[tid];
    }

    // cooperative halo tile load (zero-padded SAME); interior blocks skip predication
    const bool interior = (x0 > 0) && (x0 + BX < WID) && (y0 > 0) && (y0 + BY * RPT < HGT);
    if (interior) {
        #pragma unroll
        for (int i = tid; i < TILE_H * TILE_W; i += NT) {
            int r  = i / TILE_W;
            int c  = i - r * TILE_W;
            tile[r][c] = __ldg(&img[(y0 + r - 1) * WID + (x0 + c - 1)]);
        }
    } else {
        #pragma unroll
        for (int i = tid; i < TILE_H * TILE_W; i += NT) {
            int r  = i / TILE_W;
            int c  = i - r * TILE_W;
            int gy = y0 + r - 1;
            int gx = x0 + c - 1;
            float v = 0.0f;
            if ((unsigned)gy < HGT && (unsigned)gx < WID)
                v = __ldg(&img[gy * WID + gx]);
            tile[r][c] = v;
        }
    }
    __syncthreads();

    // softmax weights (normalized) in registers
    float W0 = s_w[0], W1 = s_w[1], W2 = s_w[2];
    float W3 = s_w[3], W4 = s_w[4], W5 = s_w[5];
    float W6 = s_w[6], W7 = s_w[7], W8 = s_w[8];
    {
        float inv = __fdividef(1.0f, ((W0+W1)+(W2+W3)) + ((W4+W5)+(W6+W7)) + W8);
        W0*=inv; W1*=inv; W2*=inv; W3*=inv; W4*=inv; W5*=inv; W6*=inv; W7*=inv; W8*=inv;
    }

    const float e0 = s_se[0], e1 = s_se[1], e2 = s_se[2];
    const float e3 = s_se[3], e4 = s_se[4], e5 = s_se[5];
    const float e6 = s_se[6], e7 = s_se[7], e8 = s_se[8];

    const bool uniform_se =
        (e0 == e1) && (e1 == e2) && (e2 == e3) && (e3 == e4) &&
        (e4 == e5) && (e5 == e6) && (e6 == e7) && (e7 == e8) && (e0 >= 0.0f);

    const int row = ty * RPT;                 // tile row of top halo for this strip
    float* outp = out + (((size_t)bb * HGT) + (y0 + row)) * WID + (x0 + tx);

    if (uniform_se) {
        // sort(s*x) = s*sort(x) for uniform s>=0: fold s into the weights,
        // operate on raw values, share row-triple sorts and pair merges.
        const float s = e0;
        W0*=s; W1*=s; W2*=s; W3*=s; W4*=s; W5*=s; W6*=s; W7*=s; W8*=s;

        float Ta0 = tile[row + 0][tx], Ta1 = tile[row + 0][tx + 1], Ta2 = tile[row + 0][tx + 2];
        float Tb0 = tile[row + 1][tx], Tb1 = tile[row + 1][tx + 1], Tb2 = tile[row + 1][tx + 2];
        SORT3(Ta0, Ta1, Ta2)
        SORT3(Tb0, Tb1, Tb2)

        #pragma unroll
        for (int k = 0; k < RPT / 2; k++) {
            float Tc0 = tile[row + 2 + 2*k][tx], Tc1 = tile[row + 2 + 2*k][tx + 1], Tc2 = tile[row + 2 + 2*k][tx + 2];
            float Td0 = tile[row + 3 + 2*k][tx], Td1 = tile[row + 3 + 2*k][tx + 1], Td2 = tile[row + 3 + 2*k][tx + 2];
            SORT3(Tc0, Tc1, Tc2)
            SORT3(Td0, Td1, Td2)

            // P = merge(Tb, copy(Tc)) ; consumes Tb, preserves Tc
            float xc0 = Tc0, xc1 = Tc1, xc2 = Tc2;
            MERGE33(Tb0, Tb1, Tb2, xc0, xc1, xc2)
            // sorted-6 P ascending: (Tb0, Tb2, Tb1, xc0, xc1, xc2)

            // pixel 2k: merge(copy(P), Ta) ; consumes Ta
            {
                float g0 = Tb0, g1 = Tb2, g2 = Tb1, g3 = xc0, g4 = xc1, g5 = xc2;
                MERGE63(g0, g1, g2, g3, g4, g5, Ta0, Ta1, Ta2)
                outp[(size_t)(2*k) * WID] = DOT63(g0, g1, g2, g3, g4, g5, Ta0, Ta1, Ta2);
            }

            // pixel 2k+1: merge(P, copy(Td)) ; consumes P, preserves Td
            {
                float h0 = Td0, h1 = Td1, h2 = Td2;
                MERGE63(Tb0, Tb2, Tb1, xc0, xc1, xc2, h0, h1, h2)
                outp[(size_t)(2*k + 1) * WID] = DOT63(Tb0, Tb2, Tb1, xc0, xc1, xc2, h0, h1, h2);
            }

            Ta0 = Tc0; Ta1 = Tc1; Ta2 = Tc2;
            Tb0 = Td0; Tb1 = Td1; Tb2 = Td2;
        }
    } else {
        // general path: per-pixel SE weighting, 25-CE optimal 9-sort
        float a0 = tile[row + 0][tx], a1 = tile[row + 0][tx + 1], a2 = tile[row + 0][tx + 2];
        float b0 = tile[row + 1][tx], b1 = tile[row + 1][tx + 1], b2 = tile[row + 1][tx + 2];

        #pragma unroll
        for (int yy = 0; yy < RPT; yy++) {
            float c0 = tile[row + 2 + yy][tx];
            float c1 = tile[row + 2 + yy][tx + 1];
            float c2 = tile[row + 2 + yy][tx + 2];

            float v0 = a0 * e0, v1 = a1 * e1, v2 = a2 * e2;
            float v3 = b0 * e3, v4 = b1 * e4, v5 = b2 * e5;
            float v6 = c0 * e6, v7 = c1 * e7, v8 = c2 * e8;

            CE(v0,v3) CE(v1,v7) CE(v2,v5) CE(v4,v8)
            CE(v0,v7) CE(v2,v4) CE(v3,v8) CE(v5,v6)
            CE(v0,v2) CE(v1,v3) CE(v4,v5) CE(v7,v8)
            CE(v1,v4) CE(v3,v6) CE(v5,v7)
            CE(v0,v1) CE(v2,v4) CE(v3,v5) CE(v6,v8)
            CE(v2,v3) CE(v4,v5) CE(v6,v7)
            CE(v1,v2) CE(v3,v4) CE(v5,v6)

            float r;
            r = v0 * W0;
            r = fmaf(v1, W1, r);
            r = fmaf(v2, W2, r);
            r = fmaf(v3, W3, r);
            r = fmaf(v4, W4, r);
            r = fmaf(v5, W5, r);
            r = fmaf(v6, W6, r);
            r = fmaf(v7, W7, r);
            r = fmaf(v8, W8, r);

            outp[(size_t)yy * WID] = r;

            a0 = b0; a1 = b1; a2 = b2;
            b0 = c0; b1 = c1; b2 = c2;
        }
    }
}

extern "C" void kernel_launch(void* const* d_in, const int* in_sizes, int n_in,
                              void* d_out, int out_size)
{
    const float* x   = (const float*)d_in[0];
    const float* se  = (const float*)d_in[1];
    const float* rnk = (const float*)d_in[2];
    float* out       = (float*)d_out;

    dim3 block(BX, BY);
    dim3 grid(WID / BX, HGT / (BY * RPT), 32);
    morph2d_kernel<<<grid, block>>>(x, se, rnk, out);
}

// round 11
// speedup vs baseline: 1.0890x; 1.0890x over previous
#include <cuda_runtime.h>
#include <cuda_bf16.h>

#define HGT 512
#define WID 512
#define TXN 16                   // threads in x
#define BY  8                    // threads in y
#define PPT 2                    // pixels per thread (horizontal)
#define RPT 4                    // rows (iterations) per thread
#define NT  (TXN*BY)             // 128 threads
#define TILE_W (TXN*PPT + 2)     // 34
#define TILE_H (BY*RPT + 2)      // 34

// compare-exchange: a<-min, b<-max  (2x FMNMX, alu pipe)
#define CE(a,b) { float lo_ = fminf(a,b); float hi_ = fmaxf(a,b); a = lo_; b = hi_; }

// first 22 comparators of the optimal 25-CE 9-sort.
// Afterward ascending order is: v0, min(v1,v2), max(v1,v2),
//   min(v3,v4), max(v3,v4), min(v5,v6), max(v5,v6), v7, v8.
#define SORT22(v0,v1,v2,v3,v4,v5,v6,v7,v8) { \
    CE(v0,v3) CE(v1,v7) CE(v2,v5) CE(v4,v8) \
    CE(v0,v7) CE(v2,v4) CE(v3,v8) CE(v5,v6) \
    CE(v0,v2) CE(v1,v3) CE(v4,v5) CE(v7,v8) \
    CE(v1,v4) CE(v3,v6) CE(v5,v7) \
    CE(v0,v1) CE(v2,v4) CE(v3,v5) CE(v6,v8) \
    CE(v2,v3) CE(v4,v5) CE(v6,v7) }

__global__ __launch_bounds__(NT, 10) void morph2d_kernel(
    const float* __restrict__ x,
    const float* __restrict__ se,
    const float* __restrict__ rnk,
    float* __restrict__ out)
{
    __shared__ float tile[TILE_H][TILE_W];
    __shared__ float s_w[9];     // exp(rank) numerators
    __shared__ float s_se[9];

    const int tx  = threadIdx.x;          // 0..15
    const int ty  = threadIdx.y;          // 0..7
    const int tid = ty * TXN + tx;
    const int bb  = blockIdx.z;
    const int x0  = blockIdx.x * (TXN * PPT);
    const int y0  = blockIdx.y * (BY * RPT);

    const float* img = x + (size_t)bb * (HGT * WID);

    if (tid < 9) {
        s_w[tid]  = __expf(rnk[tid]);
        s_se[tid] = se[tid];
    }

    // cooperative halo tile load (zero-padded SAME); interior blocks unpredicated
    const bool interior = (x0 > 0) && (x0 + TXN * PPT < WID) &&
                          (y0 > 0) && (y0 + BY * RPT < HGT);
    if (interior) {
        #pragma unroll
        for (int i = tid; i < TILE_H * TILE_W; i += NT) {
            int r = i / TILE_W;
            int c = i - r * TILE_W;
            tile[r][c] = __ldg(&img[(y0 + r - 1) * WID + (x0 + c - 1)]);
        }
    } else {
        #pragma unroll
        for (int i = tid; i < TILE_H * TILE_W; i += NT) {
            int r  = i / TILE_W;
            int c  = i - r * TILE_W;
            int gy = y0 + r - 1;
            int gx = x0 + c - 1;
            float v = 0.0f;
            if ((unsigned)gy < HGT && (unsigned)gx < WID)
                v = __ldg(&img[gy * WID + gx]);
            tile[r][c] = v;
        }
    }
    __syncthreads();

    // normalized softmax weights, with the final sort layer folded analytically:
    //   W1*min + W2*max = A1*(a+b) + B1*|a-b|,  A=(Wi+Wj)/2, B=(Wj-Wi)/2
    float W0 = s_w[0], W1 = s_w[1], W2 = s_w[2];
    float W3 = s_w[3], W4 = s_w[4], W5 = s_w[5];
    float W6 = s_w[6], W7 = s_w[7], W8 = s_w[8];
    {
        float inv = __fdividef(1.0f, ((W0+W1)+(W2+W3)) + ((W4+W5)+(W6+W7)) + W8);
        W0*=inv; W1*=inv; W2*=inv; W3*=inv; W4*=inv; W5*=inv; W6*=inv; W7*=inv; W8*=inv;
    }
    const float P0 = W0, P7 = W7, P8 = W8;
    const float A1 = 0.5f*(W1+W2), B1 = 0.5f*(W2-W1);
    const float A3 = 0.5f*(W3+W4), B3 = 0.5f*(W4-W3);
    const float A5 = 0.5f*(W5+W6), B5 = 0.5f*(W6-W5);

    const float e0 = s_se[0], e1 = s_se[1], e2 = s_se[2];
    const float e3 = s_se[3], e4 = s_se[4], e5 = s_se[5];
    const float e6 = s_se[6], e7 = s_se[7], e8 = s_se[8];

    const int row = ty * RPT;            // top halo row of this thread's strip
    const int cc  = 2 * tx;              // leftmost window column in tile

    // rolling window rows, 4 columns each, as float2 pairs
    float2 a0 = *(const float2*)&tile[row + 0][cc];
    float2 a1 = *(const float2*)&tile[row + 0][cc + 2];
    float2 b0 = *(const float2*)&tile[row + 1][cc];
    float2 b1 = *(const float2*)&tile[row + 1][cc + 2];

    float2* outp = (float2*)(out + (((size_t)bb * HGT) + (y0 + row)) * WID + (x0 + cc));

    #pragma unroll
    for (int i = 0; i < RPT; i++) {
        float2 c0 = *(const float2*)&tile[row + 2 + i][cc];
        float2 c1 = *(const float2*)&tile[row + 2 + i][cc + 2];

        // pixel v at column cc+0: window cols (0,1,2); se applied (also makes the copy)
        float v0 = a0.x * e0, v1 = a0.y * e1, v2 = a1.x * e2;
        float v3 = b0.x * e3, v4 = b0.y * e4, v5 = b1.x * e5;
        float v6 = c0.x * e6, v7 = c0.y * e7, v8 = c1.x * e8;
        // pixel u at column cc+1: window cols (1,2,3)
        float u0 = a0.y * e0, u1 = a1.x * e1, u2 = a1.y * e2;
        float u3 = b0.y * e3, u4 = b1.x * e4, u5 = b1.y * e5;
        float u6 = c0.y * e6, u7 = c1.x * e7, u8 = c1.y * e8;

        SORT22(v0, v1, v2, v3, v4, v5, v6, v7, v8)
        SORT22(u0, u1, u2, u3, u4, u5, u6, u7, u8)

        float2 o;
        {
            float s1 = v1 + v2, d1 = v1 - v2;
            float s3 = v3 + v4, d3 = v3 - v4;
            float s5 = v5 + v6, d5 = v5 - v6;
            float ra = fmaf(v0, P0, fmaf(s1, A1, fabsf(d1) * B1));
            float rb = fmaf(s3, A3, fmaf(fabsf(d3), B3, s5 * A5));
            float rc = fmaf(fabsf(d5), B5, fmaf(v7, P7, v8 * P8));
            o.x = (ra + rb) + rc;
        }
        {
            float s1 = u1 + u2, d1 = u1 - u2;
            float s3 = u3 + u4, d3 = u3 - u4;
            float s5 = u5 + u6, d5 = u5 - u6;
            float ra = fmaf(u0, P0, fmaf(s1, A1, fabsf(d1) * B1));
            float rb = fmaf(s3, A3, fmaf(fabsf(d3), B3, s5 * A5));
            float rc = fmaf(fabsf(d5), B5, fmaf(u7, P7, u8 * P8));
            o.y = (ra + rb) + rc;
        }
        outp[(size_t)i * (WID / 2)] = o;

        // roll the window down
        a0 = b0; a1 = b1;
        b0 = c0; b1 = c1;
    }
}

extern "C" void kernel_launch(void* const* d_in, const int* in_sizes, int n_in,
                              void* d_out, int out_size)
{
    const float* x   = (const float*)d_in[0];
    const float* se  = (const float*)d_in[1];
    const float* rnk = (const float*)d_in[2];
    float* out       = (float*)d_out;

    dim3 block(TXN, BY);
    dim3 grid(WID / (TXN * PPT), HGT / (BY * RPT), 32);
    morph2d_kernel<<<grid, block>>>(x, se, rnk, out);
}

// round 13
// speedup vs baseline: 1.1344x; 1.0417x over previous
#include <cuda_runtime.h>
#include <cuda_bf16.h>

#define HGT 512
#define WID 512
#define BX  32
#define BY  4
#define RPT 8                    // rows (pixels) per thread
#define NT  (BX*BY)              // 128 threads
#define TILE_W (BX + 2)          // 34
#define TILE_H (BY*RPT + 2)      // 34

// compare-exchange: a<-min, b<-max  (2x FMNMX, alu pipe)
#define CE(a,b) { float lo_ = fminf(a,b); float hi_ = fmaxf(a,b); a = lo_; b = hi_; }

// first 22 comparators of the optimal 25-CE 9-sort.
// Afterward ascending order is: v0, {v1,v2} unordered, {v3,v4} unordered,
// {v5,v6} unordered, v7, v8  (pairs resolved analytically in the dot).
#define SORT22(v0,v1,v2,v3,v4,v5,v6,v7,v8) { \
    CE(v0,v3) CE(v1,v7) CE(v2,v5) CE(v4,v8) \
    CE(v0,v7) CE(v2,v4) CE(v3,v8) CE(v5,v6) \
    CE(v0,v2) CE(v1,v3) CE(v4,v5) CE(v7,v8) \
    CE(v1,v4) CE(v3,v6) CE(v5,v7) \
    CE(v0,v1) CE(v2,v4) CE(v3,v5) CE(v6,v8) \
    CE(v2,v3) CE(v4,v5) CE(v6,v7) }

__global__ __launch_bounds__(NT, 14) void morph2d_kernel(
    const float* __restrict__ x,
    const float* __restrict__ se,
    const float* __restrict__ rnk,
    float* __restrict__ out)
{
    __shared__ float tile[TILE_H][TILE_W];
    __shared__ float s_w[9];     // exp(rank) numerators
    __shared__ float s_se[9];

    const int tx  = threadIdx.x;
    const int ty  = threadIdx.y;
    const int tid = ty * BX + tx;
    const int bb  = blockIdx.z;
    const int x0  = blockIdx.x * BX;
    const int y0  = blockIdx.y * (BY * RPT);

    const float* img = x + (size_t)bb * (HGT * WID);

    if (tid < 9) {
        s_w[tid]  = __expf(rnk[tid]);
        s_se[tid] = se[tid];
    }

    // cooperative halo tile load (zero-padded SAME); interior blocks unpredicated
    const bool interior = (x0 > 0) && (x0 + BX < WID) && (y0 > 0) && (y0 + BY * RPT < HGT);
    if (interior) {
        #pragma unroll
        for (int i = tid; i < TILE_H * TILE_W; i += NT) {
            int r = i / TILE_W;
            int c = i - r * TILE_W;
            tile[r][c] = __ldg(&img[(y0 + r - 1) * WID + (x0 + c - 1)]);
        }
    } else {
        #pragma unroll
        for (int i = tid; i < TILE_H * TILE_W; i += NT) {
            int r  = i / TILE_W;
            int c  = i - r * TILE_W;
            int gy = y0 + r - 1;
            int gx = x0 + c - 1;
            float v = 0.0f;
            if ((unsigned)gy < HGT && (unsigned)gx < WID)
                v = __ldg(&img[gy * WID + gx]);
            tile[r][c] = v;
        }
    }
    __syncthreads();

    // normalized softmax weights with final sort layer folded analytically:
    //   Wi*min + Wj*max = A*(a+b) + B*|a-b|,  A=(Wi+Wj)/2, B=(Wj-Wi)/2
    float W0 = s_w[0], W1 = s_w[1], W2 = s_w[2];
    float W3 = s_w[3], W4 = s_w[4], W5 = s_w[5];
    float W6 = s_w[6], W7 = s_w[7], W8 = s_w[8];
    {
        float inv = __fdividef(1.0f, ((W0+W1)+(W2+W3)) + ((W4+W5)+(W6+W7)) + W8);
        W0*=inv; W1*=inv; W2*=inv; W3*=inv; W4*=inv; W5*=inv; W6*=inv; W7*=inv; W8*=inv;
    }
    const float P0 = W0, P7 = W7, P8 = W8;
    const float A1 = 0.5f*(W1+W2), B1 = 0.5f*(W2-W1);
    const float A3 = 0.5f*(W3+W4), B3 = 0.5f*(W4-W3);
    const float A5 = 0.5f*(W5+W6), B5 = 0.5f*(W6-W5);

    const float e0 = s_se[0], e1 = s_se[1], e2 = s_se[2];
    const float e3 = s_se[3], e4 = s_se[4], e5 = s_se[5];
    const float e6 = s_se[6], e7 = s_se[7], e8 = s_se[8];

    const int row = ty * RPT;    // top halo row of this thread's strip

    // rolling raw window rows: a = top, b = mid
    float a0 = tile[row + 0][tx], a1 = tile[row + 0][tx + 1], a2 = tile[row + 0][tx + 2];
    float b0 = tile[row + 1][tx], b1 = tile[row + 1][tx + 1], b2 = tile[row + 1][tx + 2];

    float* outp = out + (((size_t)bb * HGT) + (y0 + row)) * WID + (x0 + tx);

    #pragma unroll
    for (int yy = 0; yy < RPT; yy++) {
        float c0 = tile[row + 2 + yy][tx];
        float c1 = tile[row + 2 + yy][tx + 1];
        float c2 = tile[row + 2 + yy][tx + 2];

        // apply SE weights (row-major window order); also serves as the copy
        float v0 = a0 * e0, v1 = a1 * e1, v2 = a2 * e2;
        float v3 = b0 * e3, v4 = b1 * e4, v5 = b2 * e5;
        float v6 = c0 * e6, v7 = c1 * e7, v8 = c2 * e8;

        SORT22(v0, v1, v2, v3, v4, v5, v6, v7, v8)

        // analytic final layer + softmax dot
        float s1 = v1 + v2, d1 = v1 - v2;
        float s3 = v3 + v4, d3 = v3 - v4;
        float s5 = v5 + v6, d5 = v5 - v6;
        float ra = fmaf(v0, P0, fmaf(s1, A1, fabsf(d1) * B1));
        float rb = fmaf(s3, A3, fmaf(fabsf(d3), B3, s5 * A5));
        float rc = fmaf(fabsf(d5), B5, fmaf(v7, P7, v8 * P8));

        outp[(size_t)yy * WID] = (ra + rb) + rc;

        // roll the window down
        a0 = b0; a1 = b1; a2 = b2;
        b0 = c0; b1 = c1; b2 = c2;
    }
}

extern "C" void kernel_launch(void* const* d_in, const int* in_sizes, int n_in,
                              void* d_out, int out_size)
{
    const float* x   = (const float*)d_in[0];
    const float* se  = (const float*)d_in[1];
    const float* rnk = (const float*)d_in[2];
    float* out       = (float*)d_out;

    dim3 block(BX, BY);
    dim3 grid(WID / BX, HGT / (BY * RPT), 32);
    morph2d_kernel<<<grid, block>>>(x, se, rnk, out);
}

// round 14
// speedup vs baseline: 1.1879x; 1.0472x over previous
#include <cuda_runtime.h>
#include <cuda_bf16.h>

#define HGT 512
#define WID 512
#define BX  32
#define BY  4
#define RPT 8                    // rows (pixels) per thread
#define NT  (BX*BY)              // 128 threads
#define TILE_W (BX + 2)          // 34
#define TILE_H (BY*RPT + 2)      // 34

// compare-exchange: a<-min, b<-max  (2x FMNMX, alu pipe)
#define CE(a,b) { float lo_ = fminf(a,b); float hi_ = fmaxf(a,b); a = lo_; b = hi_; }

__global__ __launch_bounds__(NT, 14) void morph2d_kernel(
    const float* __restrict__ x,
    const float* __restrict__ se,
    const float* __restrict__ rnk,
    float* __restrict__ out)
{
    __shared__ float tile[TILE_H][TILE_W];
    __shared__ float s_w[9];     // exp(rank) numerators
    __shared__ float s_se[9];

    const int tx  = threadIdx.x;
    const int ty  = threadIdx.y;
    const int tid = ty * BX + tx;
    const int bb  = blockIdx.z;
    const int x0  = blockIdx.x * BX;
    const int y0  = blockIdx.y * (BY * RPT);

    const float* img = x + (size_t)bb * (HGT * WID);

    if (tid < 9) {
        s_w[tid]  = __expf(rnk[tid]);
        s_se[tid] = se[tid];
    }

    // cooperative halo tile load (zero-padded SAME); interior blocks unpredicated
    const bool interior = (x0 > 0) && (x0 + BX < WID) && (y0 > 0) && (y0 + BY * RPT < HGT);
    if (interior) {
        #pragma unroll
        for (int i = tid; i < TILE_H * TILE_W; i += NT) {
            int r = i / TILE_W;
            int c = i - r * TILE_W;
            tile[r][c] = __ldg(&img[(y0 + r - 1) * WID + (x0 + c - 1)]);
        }
    } else {
        #pragma unroll
        for (int i = tid; i < TILE_H * TILE_W; i += NT) {
            int r  = i / TILE_W;
            int c  = i - r * TILE_W;
            int gy = y0 + r - 1;
            int gx = x0 + c - 1;
            float v = 0.0f;
            if ((unsigned)gy < HGT && (unsigned)gx < WID)
                v = __ldg(&img[gy * WID + gx]);
            tile[r][c] = v;
        }
    }
    __syncthreads();

    // normalized softmax weights with final sort layer folded analytically:
    //   Wi*min + Wj*max = A*(a+b) + B*|a-b|,  A=(Wi+Wj)/2, B=(Wj-Wi)/2
    float W0 = s_w[0], W1 = s_w[1], W2 = s_w[2];
    float W3 = s_w[3], W4 = s_w[4], W5 = s_w[5];
    float W6 = s_w[6], W7 = s_w[7], W8 = s_w[8];
    {
        float inv = __fdividef(1.0f, ((W0+W1)+(W2+W3)) + ((W4+W5)+(W6+W7)) + W8);
        W0*=inv; W1*=inv; W2*=inv; W3*=inv; W4*=inv; W5*=inv; W6*=inv; W7*=inv; W8*=inv;
    }

    const float e0 = s_se[0], e1 = s_se[1], e2 = s_se[2];
    const float e3 = s_se[3], e4 = s_se[4], e5 = s_se[5];
    const float e6 = s_se[6], e7 = s_se[7], e8 = s_se[8];

    const bool uniform_se =
        (e0 == e1) && (e1 == e2) && (e2 == e3) && (e3 == e4) &&
        (e4 == e5) && (e5 == e6) && (e6 == e7) && (e7 == e8) && (e0 >= 0.0f);

    const int row = ty * RPT;    // top halo row of this thread's strip

    // rolling raw window rows: a = top, b = mid
    float a0 = tile[row + 0][tx], a1 = tile[row + 0][tx + 1], a2 = tile[row + 0][tx + 2];
    float b0 = tile[row + 1][tx], b1 = tile[row + 1][tx + 1], b2 = tile[row + 1][tx + 2];

    float* outp = out + (((size_t)bb * HGT) + (y0 + row)) * WID + (x0 + tx);

    if (uniform_se) {
        // sort(s*x) = s*sort(x) for uniform s>=0: fold s into weights,
        // sort raw values with first-touch fresh registers (no copies, no FMULs).
        const float s = e0;
        const float P0 = W0 * s, P7 = W7 * s, P8 = W8 * s;
        const float A1 = 0.5f*s*(W1+W2), B1 = 0.5f*s*(W2-W1);
        const float A3 = 0.5f*s*(W3+W4), B3 = 0.5f*s*(W4-W3);
        const float A5 = 0.5f*s*(W5+W6), B5 = 0.5f*s*(W6-W5);

        #pragma unroll
        for (int yy = 0; yy < RPT; yy++) {
            float c0 = tile[row + 2 + yy][tx];
            float c1 = tile[row + 2 + yy][tx + 1];
            float c2 = tile[row + 2 + yy][tx + 2];

            // layer 1 of the 25-CE network, reading sources directly:
            // pairs (0,3)(1,7)(2,5)(4,8) over v = (a0,a1,a2,b0,b1,b2,c0,c1,c2)
            float v0 = fminf(a0, b0), v3 = fmaxf(a0, b0);
            float v1 = fminf(a1, c1), v7 = fmaxf(a1, c1);
            float v2 = fminf(a2, b2), v5 = fmaxf(a2, b2);
            float v4 = fminf(b1, c2), v8 = fmaxf(b1, c2);
            // layer 2: (0,7)(2,4)(3,8)(5,6) — v6 first-touched from c0
            CE(v0, v7) CE(v2, v4) CE(v3, v8)
            float v6 = fmaxf(v5, c0); v5 = fminf(v5, c0);
            // layers 3-6
            CE(v0,v2) CE(v1,v3) CE(v4,v5) CE(v7,v8)
            CE(v1,v4) CE(v3,v6) CE(v5,v7)
            CE(v0,v1) CE(v2,v4) CE(v3,v5) CE(v6,v8)
            CE(v2,v3) CE(v4,v5) CE(v6,v7)

            // analytic final layer + softmax dot (fma pipe)
            float s1 = v1 + v2, d1 = v1 - v2;
            float s3 = v3 + v4, d3 = v3 - v4;
            float s5 = v5 + v6, d5 = v5 - v6;
            float ra = fmaf(v0, P0, fmaf(s1, A1, fabsf(d1) * B1));
            float rb = fmaf(s3, A3, fmaf(fabsf(d3), B3, s5 * A5));
            float rc = fmaf(fabsf(d5), B5, fmaf(v7, P7, v8 * P8));

            outp[(size_t)yy * WID] = (ra + rb) + rc;

            a0 = b0; a1 = b1; a2 = b2;
            b0 = c0; b1 = c1; b2 = c2;
        }
    } else {
        // general path: per-element SE weighting (doubles as the copy)
        const float P0 = W0, P7 = W7, P8 = W8;
        const float A1 = 0.5f*(W1+W2), B1 = 0.5f*(W2-W1);
        const float A3 = 0.5f*(W3+W4), B3 = 0.5f*(W4-W3);
        const float A5 = 0.5f*(W5+W6), B5 = 0.5f*(W6-W5);

        #pragma unroll
        for (int yy = 0; yy < RPT; yy++) {
            float c0 = tile[row + 2 + yy][tx];
            float c1 = tile[row + 2 + yy][tx + 1];
            float c2 = tile[row + 2 + yy][tx + 2];

            float v0 = a0 * e0, v1 = a1 * e1, v2 = a2 * e2;
            float v3 = b0 * e3, v4 = b1 * e4, v5 = b2 * e5;
            float v6 = c0 * e6, v7 = c1 * e7, v8 = c2 * e8;

            CE(v0,v3) CE(v1,v7) CE(v2,v5) CE(v4,v8)
            CE(v0,v7) CE(v2,v4) CE(v3,v8) CE(v5,v6)
            CE(v0,v2) CE(v1,v3) CE(v4,v5) CE(v7,v8)
            CE(v1,v4) CE(v3,v6) CE(v5,v7)
            CE(v0,v1) CE(v2,v4) CE(v3,v5) CE(v6,v8)
            CE(v2,v3) CE(v4,v5) CE(v6,v7)

            float s1 = v1 + v2, d1 = v1 - v2;
            float s3 = v3 + v4, d3 = v3 - v4;
            float s5 = v5 + v6, d5 = v5 - v6;
            float ra = fmaf(v0, P0, fmaf(s1, A1, fabsf(d1) * B1));
            float rb = fmaf(s3, A3, fmaf(fabsf(d3), B3, s5 * A5));
            float rc = fmaf(fabsf(d5), B5, fmaf(v7, P7, v8 * P8));

            outp[(size_t)yy * WID] = (ra + rb) + rc;

            a0 = b0; a1 = b1; a2 = b2;
            b0 = c0; b1 = c1; b2 = c2;
        }
    }
}

extern "C" void kernel_launch(void* const* d_in, const int* in_sizes, int n_in,
                              void* d_out, int out_size)
{
    const float* x   = (const float*)d_in[0];
    const float* se  = (const float*)d_in[1];
    const float* rnk = (const float*)d_in[2];
    float* out       = (float*)d_out;

    dim3 block(BX, BY);
    dim3 grid(WID / BX, HGT / (BY * RPT), 32);
    morph2d_kernel<<<grid, block>>>(x, se, rnk, out);
}